// round 1
// baseline (speedup 1.0000x reference)
#include <cuda_runtime.h>
#include <cstdint>
#include <cstddef>

// Problem dims (fixed by the dataset)
#define NB    8
#define TT    256
#define UU    64
#define EDIM  512
#define PDIM  640
#define JD    512
#define VOCAB 1024

// Scratch for the two projections (device globals: no allocation allowed)
__device__ float g_enc_p[NB * TT * JD];    // (b*T+t, j)   2048 x 512
__device__ float g_pred_p[NB * UU * JD];   // (b*U+u, j)    512 x 512

__device__ __forceinline__ float tanh_fast(float x) {
    float y;
    asm("tanh.approx.f32 %0, %1;" : "=f"(y) : "f"(x));
    return y;
}

#define KC 16   // K-chunk per SMEM stage

// ---------------------------------------------------------------------------
// Generic projection GEMM: C[M,N] = A[M,K] @ W[K,N] + bias[N]
// 128x128 tile, 256 threads, 8x8 per-thread microtile.
// dst_sel: 0 -> g_enc_p, 1 -> g_pred_p
// ---------------------------------------------------------------------------
__global__ __launch_bounds__(256, 2)
void proj_kernel(const float* __restrict__ A, const float* __restrict__ W,
                 const float* __restrict__ bias, int dst_sel,
                 int M, int N, int K)
{
    __shared__ float As[KC][132];   // As[k][m], 132 stride: 16B-aligned rows, mild 2-way STS conflict
    __shared__ float Bs[KC][132];   // Bs[k][n]

    float* C = dst_sel ? g_pred_p : g_enc_p;

    const int tid = threadIdx.x;
    const int tx = tid & 15;        // 16 thread cols
    const int ty = tid >> 4;        // 16 thread rows
    const int row0 = blockIdx.y << 7;
    const int col0 = blockIdx.x << 7;

    float acc[8][8];
    #pragma unroll
    for (int i = 0; i < 8; i++)
        #pragma unroll
        for (int j = 0; j < 8; j++) acc[i][j] = 0.0f;

    for (int k0 = 0; k0 < K; k0 += KC) {
        // A tile: 128 rows x KC cols -> As[kk][m]; 16 threads cover one row's 16 k's (64B)
        #pragma unroll
        for (int i = tid; i < 128 * KC; i += 256) {
            int m  = i >> 4;
            int kk = i & 15;
            As[kk][m] = A[(size_t)(row0 + m) * K + k0 + kk];
        }
        // B tile: KC rows x 128 cols -> Bs[kk][n]; fully coalesced
        #pragma unroll
        for (int i = tid; i < 128 * KC; i += 256) {
            int n  = i & 127;
            int kk = i >> 7;
            Bs[kk][n] = W[(size_t)(k0 + kk) * N + col0 + n];
        }
        __syncthreads();

        #pragma unroll
        for (int kk = 0; kk < KC; kk++) {
            float4 a0 = *(const float4*)&As[kk][ty * 4];
            float4 a1 = *(const float4*)&As[kk][64 + ty * 4];
            float4 b0 = *(const float4*)&Bs[kk][tx * 4];
            float4 b1 = *(const float4*)&Bs[kk][64 + tx * 4];
            float av[8] = {a0.x, a0.y, a0.z, a0.w, a1.x, a1.y, a1.z, a1.w};
            float bv[8] = {b0.x, b0.y, b0.z, b0.w, b1.x, b1.y, b1.z, b1.w};
            #pragma unroll
            for (int i = 0; i < 8; i++)
                #pragma unroll
                for (int j = 0; j < 8; j++)
                    acc[i][j] += av[i] * bv[j];
        }
        __syncthreads();
    }

    float4 bj0 = *(const float4*)&bias[col0 + tx * 4];
    float4 bj1 = *(const float4*)&bias[col0 + 64 + tx * 4];
    float bjs[8] = {bj0.x, bj0.y, bj0.z, bj0.w, bj1.x, bj1.y, bj1.z, bj1.w};

    #pragma unroll
    for (int i = 0; i < 8; i++) {
        int r = row0 + ty * 4 + (i & 3) + ((i >> 2) << 6);
        float4 o0 = make_float4(acc[i][0] + bjs[0], acc[i][1] + bjs[1],
                                acc[i][2] + bjs[2], acc[i][3] + bjs[3]);
        float4 o1 = make_float4(acc[i][4] + bjs[4], acc[i][5] + bjs[5],
                                acc[i][6] + bjs[6], acc[i][7] + bjs[7]);
        *(float4*)&C[(size_t)r * N + col0 + tx * 4]      = o0;
        *(float4*)&C[(size_t)r * N + col0 + 64 + tx * 4] = o1;
    }
}

// ---------------------------------------------------------------------------
// Fused joint GEMM:
//   out[(bt*64+u), v] = sum_j tanh(enc_p[bt,j] + pred_p[b*64+u,j]) * W_joint[j,v] + b_joint[v]
// CTA tile: M=128 rows = 2 t-values x 64 u-values (b,t fixed pair), N=128 vocab cols.
// tanh built on the fly into the A SMEM tile (MUFU.TANH).
// ---------------------------------------------------------------------------
__global__ __launch_bounds__(256, 2)
void joint_kernel(const float* __restrict__ W_joint, const float* __restrict__ b_joint,
                  float* __restrict__ out)
{
    __shared__ float As[KC][132];
    __shared__ float Bs[KC][132];

    const int tid = threadIdx.x;
    const int tx = tid & 15;
    const int ty = tid >> 4;
    const int bt0  = blockIdx.y << 1;   // flattened (b*T + t), pair of t's; never crosses b (T even)
    const int b    = bt0 >> 8;          // T = 256
    const int col0 = blockIdx.x << 7;

    const float* encr  = g_enc_p  + (size_t)bt0 * JD;       // 2 rows
    const float* predr = g_pred_p + (size_t)b * UU * JD;    // 64 rows

    float acc[8][8];
    #pragma unroll
    for (int i = 0; i < 8; i++)
        #pragma unroll
        for (int j = 0; j < 8; j++) acc[i][j] = 0.0f;

    for (int k0 = 0; k0 < JD; k0 += KC) {
        // Build A tile with fused broadcast-add + tanh.
        // m = (t_local<<6) | u ; A[m][kk] = tanh(enc[t_local][k] + pred[u][k])
        #pragma unroll
        for (int i = tid; i < 128 * KC; i += 256) {
            int m  = i >> 4;
            int kk = i & 15;
            float e = encr [(m >> 6) * JD + k0 + kk];
            float p = predr[(m & 63) * JD + k0 + kk];
            As[kk][m] = tanh_fast(e + p);
        }
        #pragma unroll
        for (int i = tid; i < 128 * KC; i += 256) {
            int n  = i & 127;
            int kk = i >> 7;
            Bs[kk][n] = W_joint[(size_t)(k0 + kk) * VOCAB + col0 + n];
        }
        __syncthreads();

        #pragma unroll
        for (int kk = 0; kk < KC; kk++) {
            float4 a0 = *(const float4*)&As[kk][ty * 4];
            float4 a1 = *(const float4*)&As[kk][64 + ty * 4];
            float4 b0 = *(const float4*)&Bs[kk][tx * 4];
            float4 b1 = *(const float4*)&Bs[kk][64 + tx * 4];
            float av[8] = {a0.x, a0.y, a0.z, a0.w, a1.x, a1.y, a1.z, a1.w};
            float bv[8] = {b0.x, b0.y, b0.z, b0.w, b1.x, b1.y, b1.z, b1.w};
            #pragma unroll
            for (int i = 0; i < 8; i++)
                #pragma unroll
                for (int j = 0; j < 8; j++)
                    acc[i][j] += av[i] * bv[j];
        }
        __syncthreads();
    }

    float4 bj0 = *(const float4*)&b_joint[col0 + tx * 4];
    float4 bj1 = *(const float4*)&b_joint[col0 + 64 + tx * 4];
    float bjs[8] = {bj0.x, bj0.y, bj0.z, bj0.w, bj1.x, bj1.y, bj1.z, bj1.w};

    #pragma unroll
    for (int i = 0; i < 8; i++) {
        int r = ty * 4 + (i & 3) + ((i >> 2) << 6);         // local row 0..127
        size_t orow = ((size_t)bt0 * 64 + r) * VOCAB;       // (bt*64 + u) since (r>>6)*64+(r&63)=r
        float4 o0 = make_float4(acc[i][0] + bjs[0], acc[i][1] + bjs[1],
                                acc[i][2] + bjs[2], acc[i][3] + bjs[3]);
        float4 o1 = make_float4(acc[i][4] + bjs[4], acc[i][5] + bjs[5],
                                acc[i][6] + bjs[6], acc[i][7] + bjs[7]);
        *(float4*)&out[orow + col0 + tx * 4]      = o0;
        *(float4*)&out[orow + col0 + 64 + tx * 4] = o1;
    }
}

// ---------------------------------------------------------------------------
extern "C" void kernel_launch(void* const* d_in, const int* in_sizes, int n_in,
                              void* d_out, int out_size)
{
    (void)in_sizes; (void)n_in; (void)out_size;
    const float* enc_out  = (const float*)d_in[0];  // (8,256,512)
    const float* pred_out = (const float*)d_in[1];  // (8,64,640)
    const float* W_enc    = (const float*)d_in[2];  // (512,512)
    const float* b_enc    = (const float*)d_in[3];  // (512)
    const float* W_pred   = (const float*)d_in[4];  // (640,512)
    const float* b_pred   = (const float*)d_in[5];  // (512)
    const float* W_joint  = (const float*)d_in[6];  // (512,1024)
    const float* b_joint  = (const float*)d_in[7];  // (1024)
    float* out = (float*)d_out;                     // (8,256,64,1024)

    // enc projection: M=2048, N=512, K=512
    proj_kernel<<<dim3(512 / 128, 2048 / 128), 256>>>(enc_out, W_enc, b_enc, 0, 2048, 512, 512);
    // pred projection: M=512, N=512, K=640
    proj_kernel<<<dim3(512 / 128, 512 / 128), 256>>>(pred_out, W_pred, b_pred, 1, 512, 512, 640);
    // fused tanh + vocab GEMM: grid = (VOCAB/128, B*T/2)
    joint_kernel<<<dim3(VOCAB / 128, (NB * TT) / 2), 256>>>(W_joint, b_joint, out);
}

// round 6
// speedup vs baseline: 2.6510x; 2.6510x over previous
#include <cuda_runtime.h>
#include <cstdint>
#include <cstddef>

// Problem dims (fixed by the dataset)
#define NB    8
#define TT    256
#define UU    64
#define JD    512
#define VOCAB 1024

// Scratch (device globals: no allocation allowed)
__device__ float g_enc_p[NB * TT * JD];    // (b*T+t, j)   2048 x 512
__device__ float g_pred_p[NB * UU * JD];   // (b*U+u, j)    512 x 512
__device__ float g_Wt[JD * VOCAB];         // tf32-rounded W_joint, [j][v]

__device__ __forceinline__ float tanh_fast(float x) {
    float y;
    asm("tanh.approx.f32 %0, %1;" : "=f"(y) : "f"(x));
    return y;
}

__device__ __forceinline__ uint32_t cvt_tf32(float x) {
    uint32_t u;
    asm("cvt.rna.tf32.f32 %0, %1;" : "=r"(u) : "f"(x));
    return u;
}

__device__ __forceinline__ uint32_t smem_u32(const void* p) {
    uint32_t a;
    asm("{ .reg .u64 t; cvta.to.shared.u64 t, %1; cvt.u32.u64 %0, t; }" : "=r"(a) : "l"(p));
    return a;
}

__device__ __forceinline__ void mma_tf32(float (&d)[4], const uint32_t (&a)[4],
                                         const uint32_t (&b)[2]) {
    asm volatile(
        "mma.sync.aligned.m16n8k8.row.col.f32.tf32.tf32.f32 "
        "{%0,%1,%2,%3}, {%4,%5,%6,%7}, {%8,%9}, {%0,%1,%2,%3};"
        : "+f"(d[0]), "+f"(d[1]), "+f"(d[2]), "+f"(d[3])
        : "r"(a[0]), "r"(a[1]), "r"(a[2]), "r"(a[3]), "r"(b[0]), "r"(b[1]));
}

#define KC 16   // K-chunk for SIMT proj kernels

// ---------------------------------------------------------------------------
// Both projections in ONE launch.
// y in [0,16): enc  M=2048 K=512 ; y in [16,20): pred M=512 K=640. N=512 both.
// ---------------------------------------------------------------------------
__global__ __launch_bounds__(256, 2)
void proj_both(const float* __restrict__ enc, const float* __restrict__ pred,
               const float* __restrict__ We, const float* __restrict__ be,
               const float* __restrict__ Wp, const float* __restrict__ bp)
{
    __shared__ float As[KC][132];
    __shared__ float Bs[KC][132];

    const int yy = blockIdx.y;
    const float *A, *W, *bias;
    float* C;
    int K, row0;
    if (yy < 16) { A = enc;  W = We; bias = be; C = g_enc_p;  K = 512; row0 = yy << 7; }
    else         { A = pred; W = Wp; bias = bp; C = g_pred_p; K = 640; row0 = (yy - 16) << 7; }
    const int N = 512;

    const int tid = threadIdx.x;
    const int tx = tid & 15;
    const int ty = tid >> 4;
    const int col0 = blockIdx.x << 7;

    float acc[8][8];
    #pragma unroll
    for (int i = 0; i < 8; i++)
        #pragma unroll
        for (int j = 0; j < 8; j++) acc[i][j] = 0.0f;

    for (int k0 = 0; k0 < K; k0 += KC) {
        for (int i = tid; i < 128 * KC; i += 256) {
            int m  = i >> 4;
            int kk = i & 15;
            As[kk][m] = A[(size_t)(row0 + m) * K + k0 + kk];
        }
        for (int i = tid; i < 128 * KC; i += 256) {
            int n  = i & 127;
            int kk = i >> 7;
            Bs[kk][n] = W[(size_t)(k0 + kk) * N + col0 + n];
        }
        __syncthreads();

        #pragma unroll
        for (int kk = 0; kk < KC; kk++) {
            float4 a0 = *(const float4*)&As[kk][ty * 4];
            float4 a1 = *(const float4*)&As[kk][64 + ty * 4];
            float4 b0 = *(const float4*)&Bs[kk][tx * 4];
            float4 b1 = *(const float4*)&Bs[kk][64 + tx * 4];
            float av[8] = {a0.x, a0.y, a0.z, a0.w, a1.x, a1.y, a1.z, a1.w};
            float bv[8] = {b0.x, b0.y, b0.z, b0.w, b1.x, b1.y, b1.z, b1.w};
            #pragma unroll
            for (int i = 0; i < 8; i++)
                #pragma unroll
                for (int j = 0; j < 8; j++)
                    acc[i][j] += av[i] * bv[j];
        }
        __syncthreads();
    }

    float4 bj0 = *(const float4*)&bias[col0 + tx * 4];
    float4 bj1 = *(const float4*)&bias[col0 + 64 + tx * 4];
    float bjs[8] = {bj0.x, bj0.y, bj0.z, bj0.w, bj1.x, bj1.y, bj1.z, bj1.w};

    #pragma unroll
    for (int i = 0; i < 8; i++) {
        int r = row0 + ty * 4 + (i & 3) + ((i >> 2) << 6);
        float4 o0 = make_float4(acc[i][0] + bjs[0], acc[i][1] + bjs[1],
                                acc[i][2] + bjs[2], acc[i][3] + bjs[3]);
        float4 o1 = make_float4(acc[i][4] + bjs[4], acc[i][5] + bjs[5],
                                acc[i][6] + bjs[6], acc[i][7] + bjs[7]);
        *(float4*)&C[(size_t)r * N + col0 + tx * 4]      = o0;
        *(float4*)&C[(size_t)r * N + col0 + 64 + tx * 4] = o1;
    }
}

// ---------------------------------------------------------------------------
// Round W_joint to tf32 (rna) once; removes coherent truncation bias.
// ---------------------------------------------------------------------------
__global__ __launch_bounds__(256)
void prep_w(const float* __restrict__ W)
{
    int idx = blockIdx.x * 256 + threadIdx.x;
    g_Wt[idx] = __uint_as_float(cvt_tf32(W[idx]));
}

// ---------------------------------------------------------------------------
// Joint GEMM via mma.sync tf32 (STATIC shared, no cudaFuncSetAttribute):
//   out[gm, v] = sum_j tanh(enc_p[gm>>6, j] + pred_p[(gm>>12)*64 + (gm&63), j]) * W[j,v] + bj[v]
// CTA: 128x128, 8 warps (4m x 2n), warp tile 32x64, K chunks of 16, 2 stages.
// A SMEM stride 20 floats (banks 20r+c distinct mod 32); B stride 136.
// Stage = 128*20 + 16*136 = 4736 floats; double buffer = 37888 B static.
// ---------------------------------------------------------------------------
#define AST 20
#define BST 136
#define KC2 16
#define A_FLOATS (128 * AST)                    // 2560
#define B_FLOATS (KC2 * BST)                    // 2176
#define STG_FLOATS (A_FLOATS + B_FLOATS)        // 4736

__global__ __launch_bounds__(256, 2)
void joint_mma(const float* __restrict__ bj, float* __restrict__ out)
{
    __shared__ float sm[2 * STG_FLOATS];
    const uint32_t smb = smem_u32(sm);
    const int tid = threadIdx.x;
    const int wid = tid >> 5, lid = tid & 31;
    const int wm = wid & 3, wn = wid >> 2;
    const int r = lid >> 2, c = lid & 3;
    const int col0 = blockIdx.x << 7;
    const int my = blockIdx.y;              // 0..1023 (M-tile of 128 rows)
    const int bt0 = my << 1;                // two t-values, same b (T=256 even)
    const int b = bt0 >> 8;
    const float* encp  = g_enc_p  + (size_t)bt0 * JD;
    const float* predp = g_pred_p + (size_t)b * UU * JD;

    float acc[2][8][4];
    #pragma unroll
    for (int mt = 0; mt < 2; mt++)
        #pragma unroll
        for (int nt = 0; nt < 8; nt++)
            #pragma unroll
            for (int q = 0; q < 4; q++) acc[mt][nt][q] = 0.0f;

    // ---- stage fill helpers --------------------------------------------
    auto buildA = [&](int buf, int k0) {
        float* As = sm + buf * STG_FLOATS;
        #pragma unroll
        for (int j = 0; j < 2; j++) {
            int i = tid + j * 256;          // 512 float4 units: m 0..127, kg 0..3
            int m = i >> 2, kg = i & 3;
            float4 e = *(const float4*)(encp  + (size_t)(m >> 6) * JD + k0 + kg * 4);
            float4 p = *(const float4*)(predp + (size_t)(m & 63) * JD + k0 + kg * 4);
            uint32_t q0 = cvt_tf32(tanh_fast(e.x + p.x));
            uint32_t q1 = cvt_tf32(tanh_fast(e.y + p.y));
            uint32_t q2 = cvt_tf32(tanh_fast(e.z + p.z));
            uint32_t q3 = cvt_tf32(tanh_fast(e.w + p.w));
            uint4 v = make_uint4(q0, q1, q2, q3);
            *(uint4*)(As + (size_t)m * AST + kg * 4) = v;
        }
    };
    auto loadB = [&](int buf, int k0) {
        const float* src0 = g_Wt + (size_t)k0 * VOCAB + col0;
        uint32_t dst0 = smb + (buf * STG_FLOATS + A_FLOATS) * 4;
        #pragma unroll
        for (int j = 0; j < 2; j++) {
            int i = tid + j * 256;          // 512 x 16B: kk 0..15, n4 0..31
            int kk = i >> 5, n4 = i & 31;
            const float* src = src0 + (size_t)kk * VOCAB + n4 * 4;
            uint32_t dst = dst0 + (uint32_t)(kk * BST + n4 * 4) * 4;
            asm volatile("cp.async.cg.shared.global [%0], [%1], 16;" :: "r"(dst), "l"(src));
        }
        asm volatile("cp.async.commit_group;" ::: "memory");
    };

    loadB(0, 0);
    buildA(0, 0);

    for (int ch = 0; ch < 32; ch++) {
        int buf = ch & 1;
        if (ch < 31) {
            loadB(buf ^ 1, (ch + 1) * KC2);
            buildA(buf ^ 1, (ch + 1) * KC2);
            asm volatile("cp.async.wait_group 1;" ::: "memory");
        } else {
            asm volatile("cp.async.wait_group 0;" ::: "memory");
        }
        __syncthreads();

        const uint32_t* As = (const uint32_t*)(sm + buf * STG_FLOATS);
        const uint32_t* Bs = (const uint32_t*)(sm + buf * STG_FLOATS + A_FLOATS);

        #pragma unroll
        for (int ks = 0; ks < 2; ks++) {
            uint32_t a[2][4], bfr[8][2];
            #pragma unroll
            for (int mt = 0; mt < 2; mt++) {
                int row = wm * 32 + mt * 16 + r;
                const uint32_t* ap = As + (size_t)row * AST + ks * 8;
                a[mt][0] = ap[c];
                a[mt][1] = ap[8 * AST + c];
                a[mt][2] = ap[c + 4];
                a[mt][3] = ap[8 * AST + c + 4];
            }
            #pragma unroll
            for (int nt = 0; nt < 8; nt++) {
                int col = wn * 64 + nt * 8 + r;
                const uint32_t* bp = Bs + (size_t)(ks * 8 + c) * BST + col;
                bfr[nt][0] = bp[0];
                bfr[nt][1] = bp[4 * BST];
            }
            #pragma unroll
            for (int mt = 0; mt < 2; mt++)
                #pragma unroll
                for (int nt = 0; nt < 8; nt++)
                    mma_tf32(acc[mt][nt], a[mt], bfr[nt]);
        }
        __syncthreads();
    }

    // ---- epilogue: bias add + STG -------------------------------------
    const size_t gm0 = (size_t)my * 128;
    float2 bv[8];
    #pragma unroll
    for (int nt = 0; nt < 8; nt++)
        bv[nt] = *(const float2*)(bj + col0 + wn * 64 + nt * 8 + c * 2);

    #pragma unroll
    for (int mt = 0; mt < 2; mt++)
        #pragma unroll
        for (int h = 0; h < 2; h++) {
            int grow = wm * 32 + mt * 16 + h * 8 + r;
            float* op = out + (gm0 + grow) * VOCAB + col0 + wn * 64 + c * 2;
            #pragma unroll
            for (int nt = 0; nt < 8; nt++) {
                float2 o;
                o.x = acc[mt][nt][2 * h]     + bv[nt].x;
                o.y = acc[mt][nt][2 * h + 1] + bv[nt].y;
                *(float2*)(op + nt * 8) = o;
            }
        }
}

// ---------------------------------------------------------------------------
extern "C" void kernel_launch(void* const* d_in, const int* in_sizes, int n_in,
                              void* d_out, int out_size)
{
    (void)in_sizes; (void)n_in; (void)out_size;
    const float* enc_out  = (const float*)d_in[0];  // (8,256,512)
    const float* pred_out = (const float*)d_in[1];  // (8,64,640)
    const float* W_enc    = (const float*)d_in[2];  // (512,512)
    const float* b_enc    = (const float*)d_in[3];  // (512)
    const float* W_pred   = (const float*)d_in[4];  // (640,512)
    const float* b_pred   = (const float*)d_in[5];  // (512)
    const float* W_joint  = (const float*)d_in[6];  // (512,1024)
    const float* b_joint  = (const float*)d_in[7];  // (1024)
    float* out = (float*)d_out;                     // (8,256,64,1024)

    proj_both<<<dim3(4, 20), 256>>>(enc_out, pred_out, W_enc, b_enc, W_pred, b_pred);
    prep_w<<<(JD * VOCAB) / 256, 256>>>(W_joint);
    joint_mma<<<dim3(VOCAB / 128, (NB * TT * UU) / 128), 256>>>(b_joint, out);
}

// round 7
// speedup vs baseline: 3.4013x; 1.2830x over previous
#include <cuda_runtime.h>
#include <cuda_fp16.h>
#include <cstdint>
#include <cstddef>

// Problem dims (fixed by the dataset)
#define NB    8
#define TT    256
#define UU    64
#define JD    512
#define VOCAB 1024

// Scratch (device globals: no allocation allowed)
__device__ float g_enc_p[NB * TT * JD];                 // (b*T+t, j)  2048 x 512
__device__ float g_pred_p[NB * UU * JD];                // (b*U+u, j)   512 x 512
__device__ __align__(16) __half g_Wh[VOCAB * JD];       // W_joint^T fp16, [v][j]

__device__ __forceinline__ float tanh_fast(float x) {
    float y;
    asm("tanh.approx.f32 %0, %1;" : "=f"(y) : "f"(x));
    return y;
}

__device__ __forceinline__ uint32_t smem_u32(const void* p) {
    uint32_t a;
    asm("{ .reg .u64 t; cvta.to.shared.u64 t, %1; cvt.u32.u64 %0, t; }" : "=r"(a) : "l"(p));
    return a;
}

__device__ __forceinline__ void ldsm4(uint4& v, uint32_t a) {
    asm volatile("ldmatrix.sync.aligned.m8n8.x4.shared.b16 {%0,%1,%2,%3}, [%4];"
                 : "=r"(v.x), "=r"(v.y), "=r"(v.z), "=r"(v.w) : "r"(a));
}

__device__ __forceinline__ void mma_fp16(float (&d)[4], const uint4& a,
                                         uint32_t b0, uint32_t b1) {
    asm volatile(
        "mma.sync.aligned.m16n8k16.row.col.f32.f16.f16.f32 "
        "{%0,%1,%2,%3},{%4,%5,%6,%7},{%8,%9},{%0,%1,%2,%3};"
        : "+f"(d[0]), "+f"(d[1]), "+f"(d[2]), "+f"(d[3])
        : "r"(a.x), "r"(a.y), "r"(a.z), "r"(a.w), "r"(b0), "r"(b1));
}

#define KC 16   // K-chunk for SIMT proj kernel

// ---------------------------------------------------------------------------
// Both projections, 64x128 tiles -> 160 CTAs (fills the chip).
// y in [0,32): enc  M=2048 K=512 ; y in [32,40): pred M=512 K=640. N=512 both.
// ---------------------------------------------------------------------------
__global__ __launch_bounds__(256, 2)
void proj_both(const float* __restrict__ enc, const float* __restrict__ pred,
               const float* __restrict__ We, const float* __restrict__ be,
               const float* __restrict__ Wp, const float* __restrict__ bp)
{
    __shared__ float As[KC][68];
    __shared__ float Bs[KC][132];

    const int yy = blockIdx.y;
    const float *A, *W, *bias;
    float* C;
    int K, row0;
    if (yy < 32) { A = enc;  W = We; bias = be; C = g_enc_p;  K = 512; row0 = yy << 6; }
    else         { A = pred; W = Wp; bias = bp; C = g_pred_p; K = 640; row0 = (yy - 32) << 6; }
    const int N = 512;

    const int tid = threadIdx.x;
    const int tx = tid & 15;
    const int ty = tid >> 4;
    const int col0 = blockIdx.x << 7;

    float acc[4][8];
    #pragma unroll
    for (int i = 0; i < 4; i++)
        #pragma unroll
        for (int j = 0; j < 8; j++) acc[i][j] = 0.0f;

    for (int k0 = 0; k0 < K; k0 += KC) {
        for (int i = tid; i < 64 * KC; i += 256) {
            int m  = i >> 4;
            int kk = i & 15;
            As[kk][m] = A[(size_t)(row0 + m) * K + k0 + kk];
        }
        for (int i = tid; i < 128 * KC; i += 256) {
            int n  = i & 127;
            int kk = i >> 7;
            Bs[kk][n] = W[(size_t)(k0 + kk) * N + col0 + n];
        }
        __syncthreads();

        #pragma unroll
        for (int kk = 0; kk < KC; kk++) {
            float4 a0 = *(const float4*)&As[kk][ty * 4];
            float4 b0 = *(const float4*)&Bs[kk][tx * 4];
            float4 b1 = *(const float4*)&Bs[kk][64 + tx * 4];
            float av[4] = {a0.x, a0.y, a0.z, a0.w};
            float bv[8] = {b0.x, b0.y, b0.z, b0.w, b1.x, b1.y, b1.z, b1.w};
            #pragma unroll
            for (int i = 0; i < 4; i++)
                #pragma unroll
                for (int j = 0; j < 8; j++)
                    acc[i][j] += av[i] * bv[j];
        }
        __syncthreads();
    }

    float4 bj0 = *(const float4*)&bias[col0 + tx * 4];
    float4 bj1 = *(const float4*)&bias[col0 + 64 + tx * 4];
    float bjs[8] = {bj0.x, bj0.y, bj0.z, bj0.w, bj1.x, bj1.y, bj1.z, bj1.w};

    #pragma unroll
    for (int i = 0; i < 4; i++) {
        int r = row0 + ty * 4 + i;
        float4 o0 = make_float4(acc[i][0] + bjs[0], acc[i][1] + bjs[1],
                                acc[i][2] + bjs[2], acc[i][3] + bjs[3]);
        float4 o1 = make_float4(acc[i][4] + bjs[4], acc[i][5] + bjs[5],
                                acc[i][6] + bjs[6], acc[i][7] + bjs[7]);
        *(float4*)&C[(size_t)r * N + col0 + tx * 4]      = o0;
        *(float4*)&C[(size_t)r * N + col0 + 64 + tx * 4] = o1;
    }
}

// ---------------------------------------------------------------------------
// W_joint [j][v] f32 -> g_Wh [v][j] fp16 (transpose + round, once).
// ---------------------------------------------------------------------------
__global__ __launch_bounds__(256)
void prep_w(const float* __restrict__ W)
{
    int idx = blockIdx.x * 256 + threadIdx.x;   // j*1024 + v (coalesced read)
    int j = idx >> 10, v = idx & 1023;
    g_Wh[(size_t)v * JD + j] = __float2half_rn(W[idx]);
}

// ---------------------------------------------------------------------------
// Joint GEMM via mma.sync fp16 m16n8k16 + ldmatrix:
//   out[gm,v] = sum_j tanh(enc_p ⊕ pred_p)[gm,j] * W[j,v] + bj[v]
// CTA 128x128, 8 warps (4m x 2n), warp 32x64. K chunks of 32, double buffered.
// SMEM rows of 32 fp16 padded to stride 40 (80 B) -> ldmatrix conflict-free.
// A built in-loop (tanh fused), issued AFTER MMAs to overlap tensor work.
// ---------------------------------------------------------------------------
#define STRD 40                      // halves per SMEM row (80 B)
#define KC2  32
#define A_H  (128 * STRD)            // 5120 halves
#define B_H  (128 * STRD)            // 5120 halves
#define STG_H (A_H + B_H)            // 10240 halves = 20480 B per stage

__global__ __launch_bounds__(256, 2)
void joint_mma(const float* __restrict__ bj, float* __restrict__ out)
{
    __shared__ __align__(16) __half smh[2 * STG_H];   // 40960 B static
    const uint32_t smb = smem_u32(smh);
    const int tid = threadIdx.x;
    const int wid = tid >> 5, lid = tid & 31;
    const int wm = wid & 3, wn = wid >> 2;
    const int r = lid >> 2, c = lid & 3;
    const int col0 = blockIdx.x << 7;
    const int my = blockIdx.y;              // M-tile of 128 rows
    const int bt0 = my << 1;                // two t-values, same b (T=256 even)
    const int b = bt0 >> 8;
    const float* encp  = g_enc_p  + (size_t)bt0 * JD;
    const float* predp = g_pred_p + (size_t)b * UU * JD;

    float acc[2][8][4];
    #pragma unroll
    for (int mt = 0; mt < 2; mt++)
        #pragma unroll
        for (int nt = 0; nt < 8; nt++)
            #pragma unroll
            for (int q = 0; q < 4; q++) acc[mt][nt][q] = 0.0f;

    // ldmatrix per-lane base addresses (bytes)
    const int rA = (lid & 7) + ((lid >> 3) & 1) * 8;        // row within 16-row tile
    const int kA = (lid >> 4) * 8;                          // k offset 0/8
    const uint32_t aBase = smb + 2 * ((wm * 32 + rA) * STRD + kA);
    const int rB = (lid & 7) + (lid >> 4) * 8;              // n within 16-col pair
    const int kB = ((lid >> 3) & 1) * 8;
    const uint32_t bBase = smb + 2 * (A_H + (wn * 64 + rB) * STRD + kB);

    // ---- stage fill helpers --------------------------------------------
    auto buildA = [&](int buf, int k0) {
        int m = tid >> 1;
        int kh = (tid & 1) * 16;
        const float* er = encp  + (size_t)(m >> 6) * JD + k0 + kh;
        const float* pr = predp + (size_t)(m & 63) * JD + k0 + kh;
        uint32_t h[8];
        #pragma unroll
        for (int q = 0; q < 4; q++) {
            float4 e = *(const float4*)(er + q * 4);
            float4 p = *(const float4*)(pr + q * 4);
            __half2 h0 = __floats2half2_rn(tanh_fast(e.x + p.x), tanh_fast(e.y + p.y));
            __half2 h1 = __floats2half2_rn(tanh_fast(e.z + p.z), tanh_fast(e.w + p.w));
            h[q * 2]     = *(uint32_t*)&h0;
            h[q * 2 + 1] = *(uint32_t*)&h1;
        }
        __half* dst = smh + buf * STG_H + m * STRD + kh;
        *(uint4*)dst       = make_uint4(h[0], h[1], h[2], h[3]);
        *(uint4*)(dst + 8) = make_uint4(h[4], h[5], h[6], h[7]);
    };
    auto loadB = [&](int buf, int k0) {
        const __half* src0 = g_Wh + (size_t)col0 * JD + k0;
        uint32_t dst0 = smb + 2 * (buf * STG_H + A_H);
        #pragma unroll
        for (int j = 0; j < 2; j++) {
            int i = tid + j * 256;          // 512 x 16B: n 0..127, q 0..3
            int n = i >> 2, q = i & 3;
            const __half* src = src0 + (size_t)n * JD + q * 8;
            uint32_t dst = dst0 + (uint32_t)(n * STRD + q * 8) * 2;
            asm volatile("cp.async.cg.shared.global [%0], [%1], 16;" :: "r"(dst), "l"(src));
        }
        asm volatile("cp.async.commit_group;" ::: "memory");
    };

    loadB(0, 0);
    buildA(0, 0);

    for (int ch = 0; ch < 16; ch++) {
        int buf = ch & 1;
        if (ch < 15) loadB(buf ^ 1, (ch + 1) * KC2);
        if (ch < 15) {
            asm volatile("cp.async.wait_group 1;" ::: "memory");
        } else {
            asm volatile("cp.async.wait_group 0;" ::: "memory");
        }
        __syncthreads();

        const uint32_t stgOff = (uint32_t)buf * (2 * STG_H);
        #pragma unroll
        for (int ks = 0; ks < 2; ks++) {
            uint4 av[2];
            #pragma unroll
            for (int mt = 0; mt < 2; mt++)
                ldsm4(av[mt], aBase + stgOff + (uint32_t)(mt * 16 * STRD + ks * 16) * 2);
            #pragma unroll
            for (int p = 0; p < 4; p++) {
                uint4 bv;
                ldsm4(bv, bBase + stgOff + (uint32_t)(p * 16 * STRD + ks * 16) * 2);
                #pragma unroll
                for (int mt = 0; mt < 2; mt++) {
                    mma_fp16(acc[mt][2 * p],     av[mt], bv.x, bv.y);
                    mma_fp16(acc[mt][2 * p + 1], av[mt], bv.z, bv.w);
                }
            }
        }
        // Build next A while HMMAs drain (writes buf^1; readers of buf unaffected)
        if (ch < 15) buildA(buf ^ 1, (ch + 1) * KC2);
        __syncthreads();
    }

    // ---- epilogue: bias add + STG -------------------------------------
    const size_t gm0 = (size_t)my * 128;
    float2 bv[8];
    #pragma unroll
    for (int nt = 0; nt < 8; nt++)
        bv[nt] = *(const float2*)(bj + col0 + wn * 64 + nt * 8 + c * 2);

    #pragma unroll
    for (int mt = 0; mt < 2; mt++)
        #pragma unroll
        for (int h = 0; h < 2; h++) {
            int grow = wm * 32 + mt * 16 + h * 8 + r;
            float* op = out + (gm0 + grow) * VOCAB + col0 + wn * 64 + c * 2;
            #pragma unroll
            for (int nt = 0; nt < 8; nt++) {
                float2 o;
                o.x = acc[mt][nt][2 * h]     + bv[nt].x;
                o.y = acc[mt][nt][2 * h + 1] + bv[nt].y;
                *(float2*)(op + nt * 8) = o;
            }
        }
}

// ---------------------------------------------------------------------------
extern "C" void kernel_launch(void* const* d_in, const int* in_sizes, int n_in,
                              void* d_out, int out_size)
{
    (void)in_sizes; (void)n_in; (void)out_size;
    const float* enc_out  = (const float*)d_in[0];  // (8,256,512)
    const float* pred_out = (const float*)d_in[1];  // (8,64,640)
    const float* W_enc    = (const float*)d_in[2];  // (512,512)
    const float* b_enc    = (const float*)d_in[3];  // (512)
    const float* W_pred   = (const float*)d_in[4];  // (640,512)
    const float* b_pred   = (const float*)d_in[5];  // (512)
    const float* W_joint  = (const float*)d_in[6];  // (512,1024)
    const float* b_joint  = (const float*)d_in[7];  // (1024)
    float* out = (float*)d_out;                     // (8,256,64,1024)

    proj_both<<<dim3(4, 40), 256>>>(enc_out, pred_out, W_enc, b_enc, W_pred, b_pred);
    prep_w<<<(JD * VOCAB) / 256, 256>>>(W_joint);
    joint_mma<<<dim3(VOCAB / 128, (NB * TT * UU) / 128), 256>>>(b_joint, out);
}

// round 10
// speedup vs baseline: 4.3455x; 1.2776x over previous
#include <cuda_runtime.h>
#include <cuda_fp16.h>
#include <cstdint>
#include <cstddef>

// Problem dims (fixed by the dataset)
#define NB    8
#define TT    256
#define UU    64
#define JD    512
#define VOCAB 1024
#define MTOT  (NB * TT * UU)                    // 131072 joint rows

// Scratch (device globals: no allocation allowed)
__device__ float g_enc_p[NB * TT * JD];                 // (b*T+t, j)  2048 x 512
__device__ float g_pred_p[NB * UU * JD];                // (b*U+u, j)   512 x 512
__device__ __align__(16) __half g_Wh[VOCAB * JD];       // W_joint^T fp16, [v][j]
__device__ __align__(16) __half g_H[(size_t)MTOT * JD]; // tanh(enc⊕pred) fp16, 134 MB

__device__ __forceinline__ float tanh_fast(float x) {
    float y;
    asm("tanh.approx.f32 %0, %1;" : "=f"(y) : "f"(x));
    return y;
}

__device__ __forceinline__ uint32_t smem_u32(const void* p) {
    uint32_t a;
    asm("{ .reg .u64 t; cvta.to.shared.u64 t, %1; cvt.u32.u64 %0, t; }" : "=r"(a) : "l"(p));
    return a;
}

__device__ __forceinline__ void ldsm4(uint4& v, uint32_t a) {
    asm volatile("ldmatrix.sync.aligned.m8n8.x4.shared.b16 {%0,%1,%2,%3}, [%4];"
                 : "=r"(v.x), "=r"(v.y), "=r"(v.z), "=r"(v.w) : "r"(a));
}

__device__ __forceinline__ void mma_fp16(float (&d)[4], const uint4& a,
                                         uint32_t b0, uint32_t b1) {
    asm volatile(
        "mma.sync.aligned.m16n8k16.row.col.f32.f16.f16.f32 "
        "{%0,%1,%2,%3},{%4,%5,%6,%7},{%8,%9},{%0,%1,%2,%3};"
        : "+f"(d[0]), "+f"(d[1]), "+f"(d[2]), "+f"(d[3])
        : "r"(a.x), "r"(a.y), "r"(a.z), "r"(a.w), "r"(b0), "r"(b1));
}

#define KC 16   // K-chunk for SIMT proj kernel

// ---------------------------------------------------------------------------
// Both projections, 64x64 tiles -> 320 CTAs, low regs -> 3-4 CTA/SM.
// y in [0,32): enc  M=2048 K=512 ; y in [32,40): pred M=512 K=640. N=512 both.
// ---------------------------------------------------------------------------
__global__ __launch_bounds__(256)
void proj_both(const float* __restrict__ enc, const float* __restrict__ pred,
               const float* __restrict__ We, const float* __restrict__ be,
               const float* __restrict__ Wp, const float* __restrict__ bp)
{
    __shared__ float As[KC][68];
    __shared__ float Bs[KC][68];

    const int yy = blockIdx.y;
    const float *A, *W, *bias;
    float* C;
    int K, row0;
    if (yy < 32) { A = enc;  W = We; bias = be; C = g_enc_p;  K = 512; row0 = yy << 6; }
    else         { A = pred; W = Wp; bias = bp; C = g_pred_p; K = 640; row0 = (yy - 32) << 6; }
    const int N = 512;

    const int tid = threadIdx.x;
    const int tx = tid & 15;
    const int ty = tid >> 4;
    const int col0 = blockIdx.x << 6;

    float acc[4][4];
    #pragma unroll
    for (int i = 0; i < 4; i++)
        #pragma unroll
        for (int j = 0; j < 4; j++) acc[i][j] = 0.0f;

    for (int k0 = 0; k0 < K; k0 += KC) {
        for (int i = tid; i < 64 * KC; i += 256) {
            int m  = i >> 4;
            int kk = i & 15;
            As[kk][m] = A[(size_t)(row0 + m) * K + k0 + kk];
        }
        for (int i = tid; i < 64 * KC; i += 256) {
            int n  = i & 63;
            int kk = i >> 6;
            Bs[kk][n] = W[(size_t)(k0 + kk) * N + col0 + n];
        }
        __syncthreads();

        #pragma unroll
        for (int kk = 0; kk < KC; kk++) {
            float4 a0 = *(const float4*)&As[kk][ty * 4];
            float4 b0 = *(const float4*)&Bs[kk][tx * 4];
            float av[4] = {a0.x, a0.y, a0.z, a0.w};
            float bv[4] = {b0.x, b0.y, b0.z, b0.w};
            #pragma unroll
            for (int i = 0; i < 4; i++)
                #pragma unroll
                for (int j = 0; j < 4; j++)
                    acc[i][j] += av[i] * bv[j];
        }
        __syncthreads();
    }

    float4 bj = *(const float4*)&bias[col0 + tx * 4];
    float bjs[4] = {bj.x, bj.y, bj.z, bj.w};

    #pragma unroll
    for (int i = 0; i < 4; i++) {
        int r = row0 + ty * 4 + i;
        float4 o = make_float4(acc[i][0] + bjs[0], acc[i][1] + bjs[1],
                               acc[i][2] + bjs[2], acc[i][3] + bjs[3]);
        *(float4*)&C[(size_t)r * N + col0 + tx * 4] = o;
    }
}

// ---------------------------------------------------------------------------
// W_joint [j][v] f32 -> g_Wh [v][j] fp16 (transpose + round, once).
// ---------------------------------------------------------------------------
__global__ __launch_bounds__(256)
void prep_w(const float* __restrict__ W)
{
    int idx = blockIdx.x * 256 + threadIdx.x;   // j*1024 + v (coalesced read)
    int j = idx >> 10, v = idx & 1023;
    g_Wh[(size_t)v * JD + j] = __float2half_rn(W[idx]);
}

// ---------------------------------------------------------------------------
// H = fp16(tanh(enc_p ⊕ pred_p)); one thread = 8 consecutive j's of one row.
// gm = bt*64 + u ; bt = gm>>6 ; b = gm>>14 ; predrow = (gm>>14)*64 + (gm&63)
// ---------------------------------------------------------------------------
__global__ __launch_bounds__(256)
void tanh_h()
{
    int idx = blockIdx.x * 256 + threadIdx.x;   // 0 .. MTOT*64-1
    int gm = idx >> 6;
    int j0 = (idx & 63) * 8;
    const float* er = g_enc_p  + (size_t)(gm >> 6) * JD + j0;
    const float* pr = g_pred_p + (size_t)((gm >> 14) * UU + (gm & 63)) * JD + j0;
    float4 e0 = *(const float4*)er;
    float4 p0 = *(const float4*)pr;
    float4 e1 = *(const float4*)(er + 4);
    float4 p1 = *(const float4*)(pr + 4);
    __half2 h0 = __floats2half2_rn(tanh_fast(e0.x + p0.x), tanh_fast(e0.y + p0.y));
    __half2 h1 = __floats2half2_rn(tanh_fast(e0.z + p0.z), tanh_fast(e0.w + p0.w));
    __half2 h2 = __floats2half2_rn(tanh_fast(e1.x + p1.x), tanh_fast(e1.y + p1.y));
    __half2 h3 = __floats2half2_rn(tanh_fast(e1.z + p1.z), tanh_fast(e1.w + p1.w));
    uint4 v = make_uint4(*(uint32_t*)&h0, *(uint32_t*)&h1, *(uint32_t*)&h2, *(uint32_t*)&h3);
    *(uint4*)(g_H + (size_t)gm * JD + j0) = v;
}

// ---------------------------------------------------------------------------
// Pure fp16 GEMM: out = H @ Wh^T + bj.  M=131072, N=1024, K=512.
// CTA 128x128, 8 warps (4m x 2n), warp 32x64. K chunks of 32, 2-stage cp.async,
// ONE __syncthreads per chunk. SMEM stride 40 halves (80 B) -> LDSM conflict-free.
// Buffer stride = STG_BYTES (fixed from R8's out-of-bounds stage offset).
// ---------------------------------------------------------------------------
#define STRD 40                      // halves per SMEM row (80 B)
#define KC2  32
#define A_H  (128 * STRD)            // 5120 halves per operand tile
#define STG_H (2 * A_H)              // A + B per stage = 10240 halves
#define STG_BYTES (STG_H * 2)        // 20480 bytes per stage

__global__ __launch_bounds__(256, 2)
void joint_mma(const float* __restrict__ bj, float* __restrict__ out)
{
    __shared__ __align__(16) __half smh[2 * STG_H];   // 40960 B static
    const uint32_t smb = smem_u32(smh);
    const int tid = threadIdx.x;
    const int wid = tid >> 5, lid = tid & 31;
    const int wm = wid & 3, wn = wid >> 2;
    const int r = lid >> 2, c = lid & 3;
    const int col0 = blockIdx.x << 7;
    const size_t gm0 = (size_t)blockIdx.y * 128;

    float acc[2][8][4];
    #pragma unroll
    for (int mt = 0; mt < 2; mt++)
        #pragma unroll
        for (int nt = 0; nt < 8; nt++)
            #pragma unroll
            for (int q = 0; q < 4; q++) acc[mt][nt][q] = 0.0f;

    // ldmatrix per-lane base addresses (bytes)
    const int rA = (lid & 7) + ((lid >> 3) & 1) * 8;
    const int kA = (lid >> 4) * 8;
    const uint32_t aBase = smb + 2 * ((wm * 32 + rA) * STRD + kA);
    const int rB = (lid & 7) + (lid >> 4) * 8;
    const int kB = ((lid >> 3) & 1) * 8;
    const uint32_t bBase = smb + 2 * (A_H + (wn * 64 + rB) * STRD + kB);

    // per-thread cp.async coords: 512 16B-units per operand: row 0..127, q 0..3
    const int ldRow = tid >> 1;
    const int ldQ2  = (tid & 1) * 2;     // q = ldQ2, ldQ2+1
    const __half* srcA = g_H  + (gm0 + ldRow) * JD + ldQ2 * 8;
    const __half* srcB = g_Wh + (size_t)(col0 + ldRow) * JD + ldQ2 * 8;
    const uint32_t dstA = smb + 2 * (uint32_t)(ldRow * STRD + ldQ2 * 8);
    const uint32_t dstB = dstA + 2 * A_H;

    auto loadStage = [&](int buf, int k0) {
        uint32_t so = (uint32_t)buf * STG_BYTES;
        asm volatile("cp.async.cg.shared.global [%0], [%1], 16;"
                     :: "r"(dstA + so), "l"(srcA + k0) : "memory");
        asm volatile("cp.async.cg.shared.global [%0], [%1], 16;"
                     :: "r"(dstA + so + 16), "l"(srcA + k0 + 8) : "memory");
        asm volatile("cp.async.cg.shared.global [%0], [%1], 16;"
                     :: "r"(dstB + so), "l"(srcB + k0) : "memory");
        asm volatile("cp.async.cg.shared.global [%0], [%1], 16;"
                     :: "r"(dstB + so + 16), "l"(srcB + k0 + 8) : "memory");
        asm volatile("cp.async.commit_group;" ::: "memory");
    };

    loadStage(0, 0);

    for (int ch = 0; ch < 16; ch++) {
        int buf = ch & 1;
        asm volatile("cp.async.wait_group 0;" ::: "memory");
        __syncthreads();
        if (ch < 15) loadStage(buf ^ 1, (ch + 1) * KC2);

        const uint32_t stgOff = (uint32_t)buf * STG_BYTES;
        #pragma unroll
        for (int ks = 0; ks < 2; ks++) {
            uint4 av[2];
            #pragma unroll
            for (int mt = 0; mt < 2; mt++)
                ldsm4(av[mt], aBase + stgOff + (uint32_t)(mt * 16 * STRD + ks * 16) * 2);
            #pragma unroll
            for (int p = 0; p < 4; p++) {
                uint4 bv;
                ldsm4(bv, bBase + stgOff + (uint32_t)(p * 16 * STRD + ks * 16) * 2);
                #pragma unroll
                for (int mt = 0; mt < 2; mt++) {
                    mma_fp16(acc[mt][2 * p],     av[mt], bv.x, bv.y);
                    mma_fp16(acc[mt][2 * p + 1], av[mt], bv.z, bv.w);
                }
            }
        }
    }

    // ---- epilogue: bias add + STG -------------------------------------
    float2 bv[8];
    #pragma unroll
    for (int nt = 0; nt < 8; nt++)
        bv[nt] = *(const float2*)(bj + col0 + wn * 64 + nt * 8 + c * 2);

    #pragma unroll
    for (int mt = 0; mt < 2; mt++)
        #pragma unroll
        for (int h = 0; h < 2; h++) {
            int grow = wm * 32 + mt * 16 + h * 8 + r;
            float* op = out + (gm0 + grow) * VOCAB + col0 + wn * 64 + c * 2;
            #pragma unroll
            for (int nt = 0; nt < 8; nt++) {
                float2 o;
                o.x = acc[mt][nt][2 * h]     + bv[nt].x;
                o.y = acc[mt][nt][2 * h + 1] + bv[nt].y;
                *(float2*)(op + nt * 8) = o;
            }
        }
}

// ---------------------------------------------------------------------------
extern "C" void kernel_launch(void* const* d_in, const int* in_sizes, int n_in,
                              void* d_out, int out_size)
{
    (void)in_sizes; (void)n_in; (void)out_size;
    const float* enc_out  = (const float*)d_in[0];  // (8,256,512)
    const float* pred_out = (const float*)d_in[1];  // (8,64,640)
    const float* W_enc    = (const float*)d_in[2];  // (512,512)
    const float* b_enc    = (const float*)d_in[3];  // (512)
    const float* W_pred   = (const float*)d_in[4];  // (640,512)
    const float* b_pred   = (const float*)d_in[5];  // (512)
    const float* W_joint  = (const float*)d_in[6];  // (512,1024)
    const float* b_joint  = (const float*)d_in[7];  // (1024)
    float* out = (float*)d_out;                     // (8,256,64,1024)

    proj_both<<<dim3(8, 40), 256>>>(enc_out, pred_out, W_enc, b_enc, W_pred, b_pred);
    prep_w<<<(JD * VOCAB) / 256, 256>>>(W_joint);
    tanh_h<<<(MTOT * 64) / 256, 256>>>();
    joint_mma<<<dim3(VOCAB / 128, MTOT / 128), 256>>>(b_joint, out);
}

// round 15
// speedup vs baseline: 4.4974x; 1.0350x over previous
#include <cuda_runtime.h>
#include <cuda_fp16.h>
#include <cstdint>
#include <cstddef>

// Problem dims (fixed by the dataset)
#define NB    8
#define TT    256
#define UU    64
#define JD    512
#define VOCAB 1024
#define MTOT  (NB * TT * UU)                    // 131072 joint rows

// Scratch (device globals: no allocation allowed)
__device__ float g_enc_p[NB * TT * JD];                 // (b*T+t, j)  2048 x 512
__device__ float g_pred_p[NB * UU * JD];                // (b*U+u, j)   512 x 512
__device__ __align__(16) __half g_Wh[VOCAB * JD];       // W_joint^T fp16, [v][j]
__device__ __align__(16) __half g_H[(size_t)MTOT * JD]; // tanh(enc⊕pred) fp16, 134 MB

__device__ __forceinline__ float tanh_fast(float x) {
    float y;
    asm("tanh.approx.f32 %0, %1;" : "=f"(y) : "f"(x));
    return y;
}

__device__ __forceinline__ uint32_t smem_u32(const void* p) {
    uint32_t a;
    asm("{ .reg .u64 t; cvta.to.shared.u64 t, %1; cvt.u32.u64 %0, t; }" : "=r"(a) : "l"(p));
    return a;
}

__device__ __forceinline__ void ldsm4(uint4& v, uint32_t a) {
    asm volatile("ldmatrix.sync.aligned.m8n8.x4.shared.b16 {%0,%1,%2,%3}, [%4];"
                 : "=r"(v.x), "=r"(v.y), "=r"(v.z), "=r"(v.w) : "r"(a));
}

__device__ __forceinline__ void mma_fp16(float (&d)[4], const uint4& a,
                                         uint32_t b0, uint32_t b1) {
    asm volatile(
        "mma.sync.aligned.m16n8k16.row.col.f32.f16.f16.f32 "
        "{%0,%1,%2,%3},{%4,%5,%6,%7},{%8,%9},{%0,%1,%2,%3};"
        : "+f"(d[0]), "+f"(d[1]), "+f"(d[2]), "+f"(d[3])
        : "r"(a.x), "r"(a.y), "r"(a.z), "r"(a.w), "r"(b0), "r"(b1));
}

#define KC 16   // K-chunk for SIMT proj kernel

// ---------------------------------------------------------------------------
// Both projections, 64x64 tiles -> 320 CTAs.
// y in [0,32): enc  M=2048 K=512 ; y in [32,40): pred M=512 K=640. N=512 both.
// ---------------------------------------------------------------------------
__global__ __launch_bounds__(256)
void proj_both(const float* __restrict__ enc, const float* __restrict__ pred,
               const float* __restrict__ We, const float* __restrict__ be,
               const float* __restrict__ Wp, const float* __restrict__ bp)
{
    __shared__ float As[KC][68];
    __shared__ float Bs[KC][68];

    const int yy = blockIdx.y;
    const float *A, *W, *bias;
    float* C;
    int K, row0;
    if (yy < 32) { A = enc;  W = We; bias = be; C = g_enc_p;  K = 512; row0 = yy << 6; }
    else         { A = pred; W = Wp; bias = bp; C = g_pred_p; K = 640; row0 = (yy - 32) << 6; }
    const int N = 512;

    const int tid = threadIdx.x;
    const int tx = tid & 15;
    const int ty = tid >> 4;
    const int col0 = blockIdx.x << 6;

    float acc[4][4];
    #pragma unroll
    for (int i = 0; i < 4; i++)
        #pragma unroll
        for (int j = 0; j < 4; j++) acc[i][j] = 0.0f;

    for (int k0 = 0; k0 < K; k0 += KC) {
        for (int i = tid; i < 64 * KC; i += 256) {
            int m  = i >> 4;
            int kk = i & 15;
            As[kk][m] = A[(size_t)(row0 + m) * K + k0 + kk];
        }
        for (int i = tid; i < 64 * KC; i += 256) {
            int n  = i & 63;
            int kk = i >> 6;
            Bs[kk][n] = W[(size_t)(k0 + kk) * N + col0 + n];
        }
        __syncthreads();

        #pragma unroll
        for (int kk = 0; kk < KC; kk++) {
            float4 a0 = *(const float4*)&As[kk][ty * 4];
            float4 b0 = *(const float4*)&Bs[kk][tx * 4];
            float av[4] = {a0.x, a0.y, a0.z, a0.w};
            float bv[4] = {b0.x, b0.y, b0.z, b0.w};
            #pragma unroll
            for (int i = 0; i < 4; i++)
                #pragma unroll
                for (int j = 0; j < 4; j++)
                    acc[i][j] += av[i] * bv[j];
        }
        __syncthreads();
    }

    float4 bj = *(const float4*)&bias[col0 + tx * 4];
    float bjs[4] = {bj.x, bj.y, bj.z, bj.w};

    #pragma unroll
    for (int i = 0; i < 4; i++) {
        int r = row0 + ty * 4 + i;
        float4 o = make_float4(acc[i][0] + bjs[0], acc[i][1] + bjs[1],
                               acc[i][2] + bjs[2], acc[i][3] + bjs[3]);
        *(float4*)&C[(size_t)r * N + col0 + tx * 4] = o;
    }
}

// ---------------------------------------------------------------------------
// W_joint [j][v] f32 -> g_Wh [v][j] fp16 (transpose + round, once).
// ---------------------------------------------------------------------------
__global__ __launch_bounds__(256)
void prep_w(const float* __restrict__ W)
{
    int idx = blockIdx.x * 256 + threadIdx.x;   // j*1024 + v (coalesced read)
    int j = idx >> 10, v = idx & 1023;
    g_Wh[(size_t)v * JD + j] = __float2half_rn(W[idx]);
}

// ---------------------------------------------------------------------------
// H = fp16(tanh(enc_p ⊕ pred_p)); one thread = 8 consecutive j's of one row.
// ---------------------------------------------------------------------------
__global__ __launch_bounds__(256)
void tanh_h()
{
    int idx = blockIdx.x * 256 + threadIdx.x;   // 0 .. MTOT*64-1
    int gm = idx >> 6;
    int j0 = (idx & 63) * 8;
    const float* er = g_enc_p  + (size_t)(gm >> 6) * JD + j0;
    const float* pr = g_pred_p + (size_t)((gm >> 14) * UU + (gm & 63)) * JD + j0;
    float4 e0 = *(const float4*)er;
    float4 p0 = *(const float4*)pr;
    float4 e1 = *(const float4*)(er + 4);
    float4 p1 = *(const float4*)(pr + 4);
    __half2 h0 = __floats2half2_rn(tanh_fast(e0.x + p0.x), tanh_fast(e0.y + p0.y));
    __half2 h1 = __floats2half2_rn(tanh_fast(e0.z + p0.z), tanh_fast(e0.w + p0.w));
    __half2 h2 = __floats2half2_rn(tanh_fast(e1.x + p1.x), tanh_fast(e1.y + p1.y));
    __half2 h3 = __floats2half2_rn(tanh_fast(e1.z + p1.z), tanh_fast(e1.w + p1.w));
    uint4 v = make_uint4(*(uint32_t*)&h0, *(uint32_t*)&h1, *(uint32_t*)&h2, *(uint32_t*)&h3);
    *(uint4*)(g_H + (size_t)gm * JD + j0) = v;
}

// ---------------------------------------------------------------------------
// Pure fp16 GEMM: out = H @ Wh^T + bj.  M=131072, N=1024, K=512.
// CTA 128x128, 8 warps (4m x 2n). K chunks of 16, THREE cp.async stages,
// prefetch distance TWO (fix of R14's buffer collision: (ch+2)%3 != ch%3).
// wait_group 1 retires the compute chunk; 1 sync per chunk.
// SMEM row stride 24 halves (48 B): LDSM rows hit banks {0,12,24,4,16,28,8,20}
// -> all 32 banks, conflict-free. 3 stages * 12288 B = 36864 B static.
// ---------------------------------------------------------------------------
#define STRD 24                      // halves per SMEM row (48 B)
#define KC2  16
#define A_H  (128 * STRD)            // 3072 halves per operand tile
#define STG_H (2 * A_H)              // A + B per stage = 6144 halves
#define STG_BYTES (STG_H * 2)        // 12288 bytes per stage
#define NSTG 3
#define NCHUNK (JD / KC2)            // 32

__global__ __launch_bounds__(256, 2)
void joint_mma(const float* __restrict__ bj, float* __restrict__ out)
{
    __shared__ __align__(16) __half smh[NSTG * STG_H];   // 36864 B static
    const uint32_t smb = smem_u32(smh);
    const int tid = threadIdx.x;
    const int wid = tid >> 5, lid = tid & 31;
    const int wm = wid & 3, wn = wid >> 2;
    const int r = lid >> 2, c = lid & 3;
    const int col0 = blockIdx.x << 7;
    const size_t gm0 = (size_t)blockIdx.y * 128;

    float acc[2][8][4];
    #pragma unroll
    for (int mt = 0; mt < 2; mt++)
        #pragma unroll
        for (int nt = 0; nt < 8; nt++)
            #pragma unroll
            for (int q = 0; q < 4; q++) acc[mt][nt][q] = 0.0f;

    // ldmatrix per-lane base addresses (bytes)
    const int rA = (lid & 7) + ((lid >> 3) & 1) * 8;
    const int kA = (lid >> 4) * 8;
    const uint32_t aBase = smb + 2 * ((wm * 32 + rA) * STRD + kA);
    const int rB = (lid & 7) + (lid >> 4) * 8;
    const int kB = ((lid >> 3) & 1) * 8;
    const uint32_t bBase = smb + 2 * (A_H + (wn * 64 + rB) * STRD + kB);

    // cp.async coords: 256 x 16B per operand: row = tid>>1 (0..127), half-chunk = tid&1
    const int ldRow = tid >> 1;
    const int ldC   = (tid & 1) * 8;     // halves
    const __half* srcA = g_H  + (gm0 + ldRow) * JD + ldC;
    const __half* srcB = g_Wh + (size_t)(col0 + ldRow) * JD + ldC;
    const uint32_t dstA = smb + 2 * (uint32_t)(ldRow * STRD + ldC);
    const uint32_t dstB = dstA + 2 * A_H;

    auto loadStage = [&](int buf, int k0) {
        uint32_t so = (uint32_t)buf * STG_BYTES;
        asm volatile("cp.async.cg.shared.global [%0], [%1], 16;"
                     :: "r"(dstA + so), "l"(srcA + k0) : "memory");
        asm volatile("cp.async.cg.shared.global [%0], [%1], 16;"
                     :: "r"(dstB + so), "l"(srcB + k0) : "memory");
        asm volatile("cp.async.commit_group;" ::: "memory");
    };

    // Prologue: chunks 0,1 -> bufs 0,1 (2 groups in flight)
    loadStage(0, 0);
    loadStage(1, KC2);

    int cbuf = 0;   // compute buffer = ch % 3
    int pbuf = 2;   // prefetch buffer = (ch+2) % 3
    for (int ch = 0; ch < NCHUNK; ch++) {
        if (ch < NCHUNK - 1) {
            asm volatile("cp.async.wait_group 1;" ::: "memory");   // retires chunk ch
        } else {
            asm volatile("cp.async.wait_group 0;" ::: "memory");
        }
        __syncthreads();   // all warps done with chunk ch-1 -> pbuf is free
        if (ch + 2 < NCHUNK) loadStage(pbuf, (ch + 2) * KC2);

        const uint32_t so = (uint32_t)cbuf * STG_BYTES;
        uint4 av[2];
        #pragma unroll
        for (int mt = 0; mt < 2; mt++)
            ldsm4(av[mt], aBase + so + (uint32_t)(mt * 16 * STRD) * 2);
        #pragma unroll
        for (int p = 0; p < 4; p++) {
            uint4 bv;
            ldsm4(bv, bBase + so + (uint32_t)(p * 16 * STRD) * 2);
            #pragma unroll
            for (int mt = 0; mt < 2; mt++) {
                mma_fp16(acc[mt][2 * p],     av[mt], bv.x, bv.y);
                mma_fp16(acc[mt][2 * p + 1], av[mt], bv.z, bv.w);
            }
        }
        cbuf = (cbuf == NSTG - 1) ? 0 : cbuf + 1;
        pbuf = (pbuf == NSTG - 1) ? 0 : pbuf + 1;
    }

    // ---- epilogue: bias add + STG -------------------------------------
    float2 bv[8];
    #pragma unroll
    for (int nt = 0; nt < 8; nt++)
        bv[nt] = *(const float2*)(bj + col0 + wn * 64 + nt * 8 + c * 2);

    #pragma unroll
    for (int mt = 0; mt < 2; mt++)
        #pragma unroll
        for (int h = 0; h < 2; h++) {
            int grow = wm * 32 + mt * 16 + h * 8 + r;
            float* op = out + (gm0 + grow) * VOCAB + col0 + wn * 64 + c * 2;
            #pragma unroll
            for (int nt = 0; nt < 8; nt++) {
                float2 o;
                o.x = acc[mt][nt][2 * h]     + bv[nt].x;
                o.y = acc[mt][nt][2 * h + 1] + bv[nt].y;
                *(float2*)(op + nt * 8) = o;
            }
        }
}

// ---------------------------------------------------------------------------
extern "C" void kernel_launch(void* const* d_in, const int* in_sizes, int n_in,
                              void* d_out, int out_size)
{
    (void)in_sizes; (void)n_in; (void)out_size;
    const float* enc_out  = (const float*)d_in[0];  // (8,256,512)
    const float* pred_out = (const float*)d_in[1];  // (8,64,640)
    const float* W_enc    = (const float*)d_in[2];  // (512,512)
    const float* b_enc    = (const float*)d_in[3];  // (512)
    const float* W_pred   = (const float*)d_in[4];  // (640,512)
    const float* b_pred   = (const float*)d_in[5];  // (512)
    const float* W_joint  = (const float*)d_in[6];  // (512,1024)
    const float* b_joint  = (const float*)d_in[7];  // (1024)
    float* out = (float*)d_out;                     // (8,256,64,1024)

    proj_both<<<dim3(8, 40), 256>>>(enc_out, pred_out, W_enc, b_enc, W_pred, b_pred);
    prep_w<<<(JD * VOCAB) / 256, 256>>>(W_joint);
    tanh_h<<<(MTOT * 64) / 256, 256>>>();
    joint_mma<<<dim3(VOCAB / 128, MTOT / 128), 256>>>(b_joint, out);
}